// round 6
// baseline (speedup 1.0000x reference)
#include <cuda_runtime.h>

// Problem constants
#define YY 5
#define NN 200000
#define GG 128
#define II 128
#define RR 3
#define BB 1024
#define KK 64
#define KTOT (RR * GG)   // 384

#define NWEFF_BLK 192    // weff-builder CTAs prepended to gather grid

// Scratch (no cudaMalloc allowed)
__device__ float g_mean[(size_t)YY * BB * KTOT];   // A matrix: [y*B+b][r*G+g]
__device__ float g_weff[KTOT * II];                // Weff:     [r*G+g][i]

// ---------------------------------------------------------------------------
// Fused kernel #1 (flattened 1D grid, 128 threads):
//   blocks [0, 192):        build g_weff (Weff[0]=sum Wcite; Weff[1..2]=Wrel)
//   blocks [192, 192+15360): gather + masked mean, one CTA per (y, r, b)
// ---------------------------------------------------------------------------
__global__ void __launch_bounds__(128) gather_mean_kernel(
        const float* __restrict__ emb,
        const void* __restrict__ nbr,
        const void* __restrict__ cnt,
        const float* __restrict__ Wrel,
        const float* __restrict__ Wcite) {
    const int bid = blockIdx.x;
    const int tid  = threadIdx.x;

    if (bid < NWEFF_BLK) {
        #pragma unroll
        for (int j = 0; j < 2; ++j) {
            int idx = bid * 256 + j * 128 + tid;
            int r  = idx / (GG * II);
            int gi = idx - r * (GG * II);
            float v;
            if (r == 0)
                v = Wcite[gi] + Wcite[GG * II + gi] + Wcite[2 * GG * II + gi];
            else
                v = Wrel[idx];
            g_weff[idx] = v;
        }
        return;
    }

    const int gid = bid - NWEFF_BLK;
    const int y   = gid / (RR * BB);
    const int rem = gid - y * (RR * BB);
    const int r   = rem >> 10;
    const int b   = rem & (BB - 1);
    const int w    = tid >> 5;
    const int lane = tid & 31;

    __shared__ int   s_is64;
    __shared__ int   s_cnt;
    __shared__ __align__(16) int   sidx[KK];
    __shared__ __align__(16) float part[4][GG];

    // dtype detection (warp 0): odd words of first 32 int64 candidates
    if (w == 0) {
        unsigned int v = ((const unsigned int*)cnt)[2 * lane + 1];
        unsigned int m = __ballot_sync(0xffffffffu, v != 0u);
        if (lane == 0) s_is64 = (m == 0u) ? 1 : 0;
    }
    __syncthreads();
    const int is64 = s_is64;

    const long long lin = ((long long)y * RR + r) * BB + b;
    if (tid == 0) {
        s_cnt = is64 ? (int)((const long long*)cnt)[lin]
                     : ((const int*)cnt)[lin];
    }
    if (tid < KK) {
        sidx[tid] = is64 ? (int)((const long long*)nbr)[lin * KK + tid]
                         : ((const int*)nbr)[lin * KK + tid];
    }
    __syncthreads();
    const int count = s_cnt;

    // float4 view of this year's embedding slab; row stride = 32 float4s
    const float4* e = (const float4*)(emb + (size_t)y * NN * GG) + lane;

    float4 acc = make_float4(0.f, 0.f, 0.f, 0.f);
    int k = w;
    for (; k + 4 < count; k += 8) {
        float4 v0 = e[(size_t)sidx[k] * 32];
        float4 v1 = e[(size_t)sidx[k + 4] * 32];
        acc.x += v0.x + v1.x;
        acc.y += v0.y + v1.y;
        acc.z += v0.z + v1.z;
        acc.w += v0.w + v1.w;
    }
    if (k < count) {
        float4 v0 = e[(size_t)sidx[k] * 32];
        acc.x += v0.x; acc.y += v0.y; acc.z += v0.z; acc.w += v0.w;
    }

    *(float4*)&part[w][lane * 4] = acc;
    __syncthreads();

    const float inv = 1.0f / (float)(count > 0 ? count : 1);
    float s = part[0][tid] + part[1][tid] + part[2][tid] + part[3][tid];
    g_mean[((size_t)y * BB + b) * KTOT + r * GG + tid] = s * inv;
}

// ---------------------------------------------------------------------------
// SGEMM: out[5120, 128] = g_mean[5120, 384] @ g_weff[384, 128]
// Tile BM=32 x BN=64, BK=32, 256 threads, grid = 160 x 2 = 320 (2 CTAs/SM).
// Warp w: rows (w&3)*8..+7, col half (w>>2)*32 + lane (1 col/thread).
// f32x2-packed accumulators over row pairs; double-buffered smem.
// ---------------------------------------------------------------------------
#define BM 32
#define BN 64
#define BK 32
#define NCHUNK (KTOT / BK)   // 12
#define APAD 8               // A row stride 40 floats -> 16B aligned

__device__ __forceinline__ unsigned long long fma2(unsigned long long a,
                                                   unsigned long long b,
                                                   unsigned long long c) {
    unsigned long long d;
    asm("fma.rn.f32x2 %0, %1, %2, %3;" : "=l"(d) : "l"(a), "l"(b), "l"(c));
    return d;
}
__device__ __forceinline__ unsigned long long dup2(float x) {
    unsigned long long d;
    unsigned int u = __float_as_uint(x);
    asm("mov.b64 %0, {%1, %1};" : "=l"(d) : "r"(u));
    return d;
}
__device__ __forceinline__ float2 unpk2(unsigned long long p) {
    unsigned int lo, hi;
    asm("mov.b64 {%0, %1}, %2;" : "=r"(lo), "=r"(hi) : "l"(p));
    return make_float2(__uint_as_float(lo), __uint_as_float(hi));
}

__global__ void __launch_bounds__(256, 2) gemm_kernel(float* __restrict__ out) {
    __shared__ __align__(16) float Ast[2][BK][BM + APAD];  // transposed A
    __shared__ __align__(16) float Ws[2][BK][BN];

    const int tid  = threadIdx.x;        // 0..255
    const int w    = tid >> 5;           // warp 0..7
    const int rg   = w & 3;              // rows rg*8..rg*8+7
    const int cg   = w >> 2;             // col half: cg*32
    const int lane = tid & 31;
    const int rowbase = (blockIdx.x >> 1) * BM;
    const int colbase = (blockIdx.x & 1) * BN;   // 0 or 64
    const int mycol   = cg * 32 + lane;          // 0..63 within tile

    unsigned long long acc[4];           // [rowpair], 1 col
    #pragma unroll
    for (int i = 0; i < 4; ++i) acc[i] = 0ull;

    const float* Ag = g_mean + (size_t)rowbase * KTOT;
    const float* Wg = g_weff + colbase;

    // staging maps (256 threads)
    const int arow = tid >> 3;           // 0..31
    const int acol = (tid & 7) << 2;     // 0,4,...,28
    const int wrow = tid >> 4;           // 0..15  (k within chunk, +16 per j)
    const int wcol = (tid & 15) << 2;    // 0..60

    float4 pa;
    float4 pw[2];

    // prologue: load + stage chunk 0
    pa = *(const float4*)(Ag + (size_t)arow * KTOT + acol);
    #pragma unroll
    for (int j = 0; j < 2; ++j)
        pw[j] = *(const float4*)(Wg + (size_t)(wrow + j * 16) * II + wcol);
    Ast[0][acol + 0][arow] = pa.x;
    Ast[0][acol + 1][arow] = pa.y;
    Ast[0][acol + 2][arow] = pa.z;
    Ast[0][acol + 3][arow] = pa.w;
    #pragma unroll
    for (int j = 0; j < 2; ++j)
        *(float4*)&Ws[0][wrow + j * 16][wcol] = pw[j];
    __syncthreads();

    for (int c = 0; c < NCHUNK; ++c) {
        const int buf = c & 1;
        const bool more = (c + 1 < NCHUNK);
        if (more) {
            const int k0 = (c + 1) * BK;
            pa = *(const float4*)(Ag + (size_t)arow * KTOT + k0 + acol);
            #pragma unroll
            for (int j = 0; j < 2; ++j)
                pw[j] = *(const float4*)(Wg + (size_t)(k0 + wrow + j * 16) * II + wcol);
        }

        #pragma unroll
        for (int kk = 0; kk < BK; ++kk) {
            ulonglong2 aP0 = *(const ulonglong2*)&Ast[buf][kk][rg * 8];      // rows 0-3
            ulonglong2 aP1 = *(const ulonglong2*)&Ast[buf][kk][rg * 8 + 4];  // rows 4-7
            unsigned long long wd = dup2(Ws[buf][kk][mycol]);

            acc[0] = fma2(aP0.x, wd, acc[0]);
            acc[1] = fma2(aP0.y, wd, acc[1]);
            acc[2] = fma2(aP1.x, wd, acc[2]);
            acc[3] = fma2(aP1.y, wd, acc[3]);
        }

        if (more) {
            const int nbuf = buf ^ 1;
            Ast[nbuf][acol + 0][arow] = pa.x;
            Ast[nbuf][acol + 1][arow] = pa.y;
            Ast[nbuf][acol + 2][arow] = pa.z;
            Ast[nbuf][acol + 3][arow] = pa.w;
            #pragma unroll
            for (int j = 0; j < 2; ++j)
                *(float4*)&Ws[nbuf][wrow + j * 16][wcol] = pw[j];
            __syncthreads();
        }
    }

    // epilogue: unpack row pairs, one float per row
    const int row0 = rowbase + rg * 8;
    float* o = out + (size_t)row0 * II + colbase + mycol;
    #pragma unroll
    for (int rp = 0; rp < 4; ++rp) {
        float2 c0 = unpk2(acc[rp]);
        o[(size_t)(2 * rp) * II]     = c0.x;
        o[(size_t)(2 * rp + 1) * II] = c0.y;
    }
}

// ---------------------------------------------------------------------------
// kernel_launch: [weff-build + gather] -> GEMM
// ---------------------------------------------------------------------------
extern "C" void kernel_launch(void* const* d_in, const int* in_sizes, int n_in,
                              void* d_out, int out_size) {
    const float* emb   = (const float*)d_in[0];
    const float* Wrel  = (const float*)d_in[1];
    const float* Wcite = (const float*)d_in[2];
    const void*  nbr   = d_in[3];
    const void*  cnt   = d_in[4];
    float* out = (float*)d_out;

    gather_mean_kernel<<<NWEFF_BLK + YY * RR * BB, 128>>>(emb, nbr, cnt, Wrel, Wcite);

    gemm_kernel<<<((YY * BB) / BM) * 2, 256>>>(out);
}

// round 7
// speedup vs baseline: 1.1758x; 1.1758x over previous
#include <cuda_runtime.h>

// Problem constants
#define YY 5
#define NN 200000
#define GG 128
#define II 128
#define RR 3
#define BB 1024
#define KK 64
#define KTOT (RR * GG)   // 384

#define NWEFF_BLK 192    // weff-builder CTAs prepended to gather grid

// Scratch (no cudaMalloc allowed)
__device__ __align__(16) float g_mean[(size_t)YY * BB * KTOT];  // [y*B+b][r*G+g]
__device__ __align__(16) float g_weff[KTOT * II];               // [r*G+g][i]

// ---------------------------------------------------------------------------
// Fused kernel #1 (flattened 1D grid, 128 threads):
//   blocks [0, 192):        build g_weff (Weff[0]=sum Wcite; Weff[1..2]=Wrel)
//   blocks [192, 192+15360): gather + masked mean, one CTA per (y, r, b)
// ---------------------------------------------------------------------------
__global__ void __launch_bounds__(128) gather_mean_kernel(
        const float* __restrict__ emb,
        const void* __restrict__ nbr,
        const void* __restrict__ cnt,
        const float* __restrict__ Wrel,
        const float* __restrict__ Wcite) {
    const int bid = blockIdx.x;
    const int tid  = threadIdx.x;

    if (bid < NWEFF_BLK) {
        #pragma unroll
        for (int j = 0; j < 2; ++j) {
            int idx = bid * 256 + j * 128 + tid;
            int r  = idx / (GG * II);
            int gi = idx - r * (GG * II);
            float v;
            if (r == 0)
                v = Wcite[gi] + Wcite[GG * II + gi] + Wcite[2 * GG * II + gi];
            else
                v = Wrel[idx];
            g_weff[idx] = v;
        }
        return;
    }

    const int gid = bid - NWEFF_BLK;
    const int y   = gid / (RR * BB);
    const int rem = gid - y * (RR * BB);
    const int r   = rem >> 10;
    const int b   = rem & (BB - 1);
    const int w    = tid >> 5;
    const int lane = tid & 31;

    __shared__ int   s_is64;
    __shared__ int   s_cnt;
    __shared__ __align__(16) int   sidx[KK];
    __shared__ __align__(16) float part[4][GG];

    // dtype detection (warp 0): odd words of first 32 int64 candidates
    if (w == 0) {
        unsigned int v = ((const unsigned int*)cnt)[2 * lane + 1];
        unsigned int m = __ballot_sync(0xffffffffu, v != 0u);
        if (lane == 0) s_is64 = (m == 0u) ? 1 : 0;
    }
    __syncthreads();
    const int is64 = s_is64;

    const long long lin = ((long long)y * RR + r) * BB + b;
    if (tid == 0) {
        s_cnt = is64 ? (int)((const long long*)cnt)[lin]
                     : ((const int*)cnt)[lin];
    }
    if (tid < KK) {
        sidx[tid] = is64 ? (int)((const long long*)nbr)[lin * KK + tid]
                         : ((const int*)nbr)[lin * KK + tid];
    }
    __syncthreads();
    const int count = s_cnt;

    // float4 view of this year's embedding slab; row stride = 32 float4s
    const float4* e = (const float4*)(emb + (size_t)y * NN * GG) + lane;

    float4 acc = make_float4(0.f, 0.f, 0.f, 0.f);
    int k = w;
    for (; k + 4 < count; k += 8) {
        float4 v0 = e[(size_t)sidx[k] * 32];
        float4 v1 = e[(size_t)sidx[k + 4] * 32];
        acc.x += v0.x + v1.x;
        acc.y += v0.y + v1.y;
        acc.z += v0.z + v1.z;
        acc.w += v0.w + v1.w;
    }
    if (k < count) {
        float4 v0 = e[(size_t)sidx[k] * 32];
        acc.x += v0.x; acc.y += v0.y; acc.z += v0.z; acc.w += v0.w;
    }

    *(float4*)&part[w][lane * 4] = acc;
    __syncthreads();

    const float inv = 1.0f / (float)(count > 0 ? count : 1);
    float s = part[0][tid] + part[1][tid] + part[2][tid] + part[3][tid];
    g_mean[((size_t)y * BB + b) * KTOT + r * GG + tid] = s * inv;
}

// ---------------------------------------------------------------------------
// SGEMM: out[5120, 128] = g_mean[5120, 384] @ g_weff[384, 128]
// Tile BM=16 x BN=128, BK=32; 128 threads (4 warps); grid = 320 (2+ CTAs/SM).
// Warp w owns rows w*4..w*4+3 (2 f32x2 rowpairs); lane owns cols lane*4..+3.
// 8 f32x2 accumulators/thread. W staged with cp.async (no register pass),
// A staged via 4 regs + transposed STS. Double-buffered, 1 sync per chunk.
// ---------------------------------------------------------------------------
#define BM 16
#define BN 128
#define BK 32
#define NCHUNK (KTOT / BK)   // 12
#define APAD 8               // A row stride 24 floats = 96B (16B-divisible)

__device__ __forceinline__ unsigned long long fma2(unsigned long long a,
                                                   unsigned long long b,
                                                   unsigned long long c) {
    unsigned long long d;
    asm("fma.rn.f32x2 %0, %1, %2, %3;" : "=l"(d) : "l"(a), "l"(b), "l"(c));
    return d;
}
__device__ __forceinline__ unsigned long long dup2(float x) {
    unsigned long long d;
    unsigned int u = __float_as_uint(x);
    asm("mov.b64 %0, {%1, %1};" : "=l"(d) : "r"(u));
    return d;
}
__device__ __forceinline__ float2 unpk2(unsigned long long p) {
    unsigned int lo, hi;
    asm("mov.b64 {%0, %1}, %2;" : "=r"(lo), "=r"(hi) : "l"(p));
    return make_float2(__uint_as_float(lo), __uint_as_float(hi));
}
__device__ __forceinline__ void cp_async16(unsigned int smem_addr,
                                           const void* gptr) {
    asm volatile("cp.async.ca.shared.global [%0], [%1], 16;\n"
                 :: "r"(smem_addr), "l"(gptr));
}
__device__ __forceinline__ void cp_async_commit() {
    asm volatile("cp.async.commit_group;\n");
}
__device__ __forceinline__ void cp_async_wait0() {
    asm volatile("cp.async.wait_group 0;\n");
}

__global__ void __launch_bounds__(128) gemm_kernel(float* __restrict__ out) {
    __shared__ __align__(16) float Ast[2][BK][BM + APAD];  // transposed A
    __shared__ __align__(16) float Ws[2][BK][BN];

    const int tid  = threadIdx.x;        // 0..127
    const int w    = tid >> 5;           // warp 0..3 -> rows w*4..w*4+3
    const int lane = tid & 31;           // cols lane*4..lane*4+3
    const int rowbase = blockIdx.x * BM;

    unsigned long long acc[2][4];        // [rowpair][col]
    #pragma unroll
    for (int i = 0; i < 2; ++i)
        #pragma unroll
        for (int j = 0; j < 4; ++j) acc[i][j] = 0ull;

    const float* Ag = g_mean + (size_t)rowbase * KTOT;

    // staging maps
    const int arow = tid >> 3;           // 0..15
    const int acol = (tid & 7) << 2;     // 0,4,...,28
    const int wrow = tid >> 5;           // 0..3   (k within chunk, +4 per j)
    const int wcol = (tid & 31) << 2;    // 0..124

    unsigned int ws_base[2];
    ws_base[0] = (unsigned int)__cvta_generic_to_shared(&Ws[0][0][0]);
    ws_base[1] = (unsigned int)__cvta_generic_to_shared(&Ws[1][0][0]);

    // prologue: stage chunk 0
    {
        float4 pa = *(const float4*)(Ag + (size_t)arow * KTOT + acol);
        Ast[0][acol + 0][arow] = pa.x;
        Ast[0][acol + 1][arow] = pa.y;
        Ast[0][acol + 2][arow] = pa.z;
        Ast[0][acol + 3][arow] = pa.w;
        #pragma unroll
        for (int j = 0; j < 8; ++j) {
            int kr = wrow + j * 4;       // 0..31
            cp_async16(ws_base[0] + (unsigned int)((kr * BN + wcol) * 4),
                       g_weff + (size_t)kr * BN + wcol);
        }
        cp_async_commit();
        cp_async_wait0();
    }
    __syncthreads();

    for (int c = 0; c < NCHUNK; ++c) {
        const int buf = c & 1;
        const bool more = (c + 1 < NCHUNK);
        float4 pa;
        if (more) {
            const int k0 = (c + 1) * BK;
            pa = *(const float4*)(Ag + (size_t)arow * KTOT + k0 + acol);
            #pragma unroll
            for (int j = 0; j < 8; ++j) {
                int kr = wrow + j * 4;
                cp_async16(ws_base[buf ^ 1] + (unsigned int)((kr * BN + wcol) * 4),
                           g_weff + (size_t)(k0 + kr) * BN + wcol);
            }
            cp_async_commit();
        }

        #pragma unroll
        for (int kk = 0; kk < BK; ++kk) {
            ulonglong2 aP = *(const ulonglong2*)&Ast[buf][kk][w * 4];  // 2 rowpairs
            float4 w4 = *(const float4*)&Ws[buf][kk][lane * 4];
            unsigned long long wd0 = dup2(w4.x), wd1 = dup2(w4.y);
            unsigned long long wd2 = dup2(w4.z), wd3 = dup2(w4.w);

            acc[0][0] = fma2(aP.x, wd0, acc[0][0]);
            acc[0][1] = fma2(aP.x, wd1, acc[0][1]);
            acc[0][2] = fma2(aP.x, wd2, acc[0][2]);
            acc[0][3] = fma2(aP.x, wd3, acc[0][3]);
            acc[1][0] = fma2(aP.y, wd0, acc[1][0]);
            acc[1][1] = fma2(aP.y, wd1, acc[1][1]);
            acc[1][2] = fma2(aP.y, wd2, acc[1][2]);
            acc[1][3] = fma2(aP.y, wd3, acc[1][3]);
        }

        if (more) {
            const int nbuf = buf ^ 1;
            Ast[nbuf][acol + 0][arow] = pa.x;
            Ast[nbuf][acol + 1][arow] = pa.y;
            Ast[nbuf][acol + 2][arow] = pa.z;
            Ast[nbuf][acol + 3][arow] = pa.w;
            cp_async_wait0();
            __syncthreads();
        }
    }

    // epilogue: unpack row pairs, float4 per row
    const int row0 = rowbase + w * 4;
    float* o = out + (size_t)row0 * BN + lane * 4;
    #pragma unroll
    for (int rp = 0; rp < 2; ++rp) {
        float2 c0 = unpk2(acc[rp][0]);
        float2 c1 = unpk2(acc[rp][1]);
        float2 c2 = unpk2(acc[rp][2]);
        float2 c3 = unpk2(acc[rp][3]);
        *(float4*)(o + (size_t)(2 * rp) * BN)     = make_float4(c0.x, c1.x, c2.x, c3.x);
        *(float4*)(o + (size_t)(2 * rp + 1) * BN) = make_float4(c0.y, c1.y, c2.y, c3.y);
    }
}

// ---------------------------------------------------------------------------
// kernel_launch: [weff-build + gather] -> GEMM
// ---------------------------------------------------------------------------
extern "C" void kernel_launch(void* const* d_in, const int* in_sizes, int n_in,
                              void* d_out, int out_size) {
    const float* emb   = (const float*)d_in[0];
    const float* Wrel  = (const float*)d_in[1];
    const float* Wcite = (const float*)d_in[2];
    const void*  nbr   = d_in[3];
    const void*  cnt   = d_in[4];
    float* out = (float*)d_out;

    gather_mean_kernel<<<NWEFF_BLK + YY * RR * BB, 128>>>(emb, nbr, cnt, Wrel, Wcite);

    gemm_kernel<<<(YY * BB) / BM, 128>>>(out);
}

// round 8
// speedup vs baseline: 1.2531x; 1.0657x over previous
#include <cuda_runtime.h>

// Problem constants
#define YY 5
#define NN 200000
#define GG 128
#define II 128
#define RR 3
#define BB 1024
#define KK 64
#define KTOT (RR * GG)   // 384

#define NWEFF_BLK 192    // weff-builder CTAs prepended to gather grid
#define NSPLIT 4         // GEMM K-split factor
#define MTOT (YY * BB)   // 5120

// Scratch (no cudaMalloc allowed)
__device__ __align__(16) float g_mean[(size_t)MTOT * KTOT];        // [m][k]
__device__ __align__(16) float g_weff[KTOT * II];                  // [k][i]
__device__ __align__(16) float g_part[NSPLIT][(size_t)MTOT * II];  // partials

// ---------------------------------------------------------------------------
// Fused kernel #1 (flattened 1D grid, 128 threads):
//   blocks [0, 192):        build g_weff (Weff[0]=sum Wcite; Weff[1..2]=Wrel)
//   blocks [192, 192+15360): gather + masked mean, one CTA per (y, r, b)
// ---------------------------------------------------------------------------
__global__ void __launch_bounds__(128) gather_mean_kernel(
        const float* __restrict__ emb,
        const void* __restrict__ nbr,
        const void* __restrict__ cnt,
        const float* __restrict__ Wrel,
        const float* __restrict__ Wcite) {
    const int bid = blockIdx.x;
    const int tid  = threadIdx.x;

    if (bid < NWEFF_BLK) {
        #pragma unroll
        for (int j = 0; j < 2; ++j) {
            int idx = bid * 256 + j * 128 + tid;
            int r  = idx / (GG * II);
            int gi = idx - r * (GG * II);
            float v;
            if (r == 0)
                v = Wcite[gi] + Wcite[GG * II + gi] + Wcite[2 * GG * II + gi];
            else
                v = Wrel[idx];
            g_weff[idx] = v;
        }
        return;
    }

    const int gid = bid - NWEFF_BLK;
    const int y   = gid / (RR * BB);
    const int rem = gid - y * (RR * BB);
    const int r   = rem >> 10;
    const int b   = rem & (BB - 1);
    const int w    = tid >> 5;
    const int lane = tid & 31;

    __shared__ int   s_is64;
    __shared__ int   s_cnt;
    __shared__ __align__(16) int   sidx[KK];
    __shared__ __align__(16) float part[4][GG];

    // dtype detection (warp 0): odd words of first 32 int64 candidates
    if (w == 0) {
        unsigned int v = ((const unsigned int*)cnt)[2 * lane + 1];
        unsigned int m = __ballot_sync(0xffffffffu, v != 0u);
        if (lane == 0) s_is64 = (m == 0u) ? 1 : 0;
    }
    __syncthreads();
    const int is64 = s_is64;

    const long long lin = ((long long)y * RR + r) * BB + b;
    if (tid == 0) {
        s_cnt = is64 ? (int)((const long long*)cnt)[lin]
                     : ((const int*)cnt)[lin];
    }
    if (tid < KK) {
        sidx[tid] = is64 ? (int)((const long long*)nbr)[lin * KK + tid]
                         : ((const int*)nbr)[lin * KK + tid];
    }
    __syncthreads();
    const int count = s_cnt;

    // float4 view of this year's embedding slab; row stride = 32 float4s
    const float4* e = (const float4*)(emb + (size_t)y * NN * GG) + lane;

    float4 acc = make_float4(0.f, 0.f, 0.f, 0.f);
    int k = w;
    for (; k + 4 < count; k += 8) {
        float4 v0 = e[(size_t)sidx[k] * 32];
        float4 v1 = e[(size_t)sidx[k + 4] * 32];
        acc.x += v0.x + v1.x;
        acc.y += v0.y + v1.y;
        acc.z += v0.z + v1.z;
        acc.w += v0.w + v1.w;
    }
    if (k < count) {
        float4 v0 = e[(size_t)sidx[k] * 32];
        acc.x += v0.x; acc.y += v0.y; acc.z += v0.z; acc.w += v0.w;
    }

    *(float4*)&part[w][lane * 4] = acc;
    __syncthreads();

    const float inv = 1.0f / (float)(count > 0 ? count : 1);
    float s = part[0][tid] + part[1][tid] + part[2][tid] + part[3][tid];
    g_mean[((size_t)y * BB + b) * KTOT + r * GG + tid] = s * inv;
}

// ---------------------------------------------------------------------------
// K-split SGEMM partials: g_part[s] = A[:, s*96:(s+1)*96] @ W[s*96:(s+1)*96, :]
// Tile BM=32 x BN=128, BK=32, 3 chunks per CTA; 128 threads (4 warps);
// grid = 160 row-tiles x 4 k-splits = 640 CTAs (~4.3 CTAs/SM, ~17 warps/SM).
// Warp w: rows w*8..w*8+7; lane: cols lane*4..+3 -> 16 f32x2 accs/thread.
// W staged with cp.async; A register-staged (transpose); double-buffered.
// ---------------------------------------------------------------------------
#define BM 32
#define BN 128
#define BK 32
#define KSPL (KTOT / NSPLIT)    // 96
#define NCHUNK (KSPL / BK)      // 3
#define APAD 8                  // A row stride 40 floats -> 16B-divisible

__device__ __forceinline__ unsigned long long fma2(unsigned long long a,
                                                   unsigned long long b,
                                                   unsigned long long c) {
    unsigned long long d;
    asm("fma.rn.f32x2 %0, %1, %2, %3;" : "=l"(d) : "l"(a), "l"(b), "l"(c));
    return d;
}
__device__ __forceinline__ unsigned long long dup2(float x) {
    unsigned long long d;
    unsigned int u = __float_as_uint(x);
    asm("mov.b64 %0, {%1, %1};" : "=l"(d) : "r"(u));
    return d;
}
__device__ __forceinline__ float2 unpk2(unsigned long long p) {
    unsigned int lo, hi;
    asm("mov.b64 {%0, %1}, %2;" : "=r"(lo), "=r"(hi) : "l"(p));
    return make_float2(__uint_as_float(lo), __uint_as_float(hi));
}
__device__ __forceinline__ void cp_async16(unsigned int smem_addr,
                                           const void* gptr) {
    asm volatile("cp.async.ca.shared.global [%0], [%1], 16;\n"
                 :: "r"(smem_addr), "l"(gptr));
}
__device__ __forceinline__ void cp_async_commit() {
    asm volatile("cp.async.commit_group;\n");
}
__device__ __forceinline__ void cp_async_wait0() {
    asm volatile("cp.async.wait_group 0;\n");
}

__global__ void __launch_bounds__(128) gemm_partial_kernel() {
    __shared__ __align__(16) float Ast[2][BK][BM + APAD];  // transposed A
    __shared__ __align__(16) float Ws[2][BK][BN];

    const int tid  = threadIdx.x;        // 0..127
    const int w    = tid >> 5;           // warp 0..3 -> rows w*8..w*8+7
    const int lane = tid & 31;           // cols lane*4..lane*4+3
    const int ksplit  = blockIdx.x & (NSPLIT - 1);
    const int rowbase = (blockIdx.x >> 2) * BM;
    const int kbase   = ksplit * KSPL;

    unsigned long long acc[4][4];        // [rowpair][col]
    #pragma unroll
    for (int i = 0; i < 4; ++i)
        #pragma unroll
        for (int j = 0; j < 4; ++j) acc[i][j] = 0ull;

    const float* Ag = g_mean + (size_t)rowbase * KTOT + kbase;
    const float* Wg = g_weff + (size_t)kbase * BN;

    // staging maps
    const int arow = tid >> 3;           // used as l>>3 below
    const int wrow = tid >> 5;           // 0..3   (k within chunk, +4 per j)
    const int wcol = (tid & 31) << 2;    // 0..124

    unsigned int ws_base[2];
    ws_base[0] = (unsigned int)__cvta_generic_to_shared(&Ws[0][0][0]);
    ws_base[1] = (unsigned int)__cvta_generic_to_shared(&Ws[1][0][0]);

    // prologue: stage chunk 0 (A: 2 float4/thread; W: 8 cp.async/thread)
    {
        #pragma unroll
        for (int j = 0; j < 2; ++j) {
            int l = tid + j * 128;
            int rr = l >> 3, kc = (l & 7) << 2;
            float4 pa = *(const float4*)(Ag + (size_t)rr * KTOT + kc);
            Ast[0][kc + 0][rr] = pa.x;
            Ast[0][kc + 1][rr] = pa.y;
            Ast[0][kc + 2][rr] = pa.z;
            Ast[0][kc + 3][rr] = pa.w;
        }
        #pragma unroll
        for (int j = 0; j < 8; ++j) {
            int kr = wrow + j * 4;       // 0..31
            cp_async16(ws_base[0] + (unsigned int)((kr * BN + wcol) * 4),
                       Wg + (size_t)kr * BN + wcol);
        }
        cp_async_commit();
        cp_async_wait0();
    }
    __syncthreads();

    for (int c = 0; c < NCHUNK; ++c) {
        const int buf = c & 1;
        const bool more = (c + 1 < NCHUNK);
        float4 pa0, pa1;
        if (more) {
            const int k0 = (c + 1) * BK;
            {
                int l = tid;
                pa0 = *(const float4*)(Ag + (size_t)(l >> 3) * KTOT + k0 + ((l & 7) << 2));
                l = tid + 128;
                pa1 = *(const float4*)(Ag + (size_t)(l >> 3) * KTOT + k0 + ((l & 7) << 2));
            }
            #pragma unroll
            for (int j = 0; j < 8; ++j) {
                int kr = wrow + j * 4;
                cp_async16(ws_base[buf ^ 1] + (unsigned int)((kr * BN + wcol) * 4),
                           Wg + (size_t)(k0 + kr) * BN + wcol);
            }
            cp_async_commit();
        }

        #pragma unroll
        for (int kk = 0; kk < BK; ++kk) {
            ulonglong2 aP0 = *(const ulonglong2*)&Ast[buf][kk][w * 8];      // rows 0-3
            ulonglong2 aP1 = *(const ulonglong2*)&Ast[buf][kk][w * 8 + 4];  // rows 4-7
            float4 w4 = *(const float4*)&Ws[buf][kk][lane * 4];
            unsigned long long wd0 = dup2(w4.x), wd1 = dup2(w4.y);
            unsigned long long wd2 = dup2(w4.z), wd3 = dup2(w4.w);

            acc[0][0] = fma2(aP0.x, wd0, acc[0][0]);
            acc[0][1] = fma2(aP0.x, wd1, acc[0][1]);
            acc[0][2] = fma2(aP0.x, wd2, acc[0][2]);
            acc[0][3] = fma2(aP0.x, wd3, acc[0][3]);
            acc[1][0] = fma2(aP0.y, wd0, acc[1][0]);
            acc[1][1] = fma2(aP0.y, wd1, acc[1][1]);
            acc[1][2] = fma2(aP0.y, wd2, acc[1][2]);
            acc[1][3] = fma2(aP0.y, wd3, acc[1][3]);
            acc[2][0] = fma2(aP1.x, wd0, acc[2][0]);
            acc[2][1] = fma2(aP1.x, wd1, acc[2][1]);
            acc[2][2] = fma2(aP1.x, wd2, acc[2][2]);
            acc[2][3] = fma2(aP1.x, wd3, acc[2][3]);
            acc[3][0] = fma2(aP1.y, wd0, acc[3][0]);
            acc[3][1] = fma2(aP1.y, wd1, acc[3][1]);
            acc[3][2] = fma2(aP1.y, wd2, acc[3][2]);
            acc[3][3] = fma2(aP1.y, wd3, acc[3][3]);
        }

        if (more) {
            const int nbuf = buf ^ 1;
            {
                int l = tid;
                int rr = l >> 3, kc = (l & 7) << 2;
                Ast[nbuf][kc + 0][rr] = pa0.x;
                Ast[nbuf][kc + 1][rr] = pa0.y;
                Ast[nbuf][kc + 2][rr] = pa0.z;
                Ast[nbuf][kc + 3][rr] = pa0.w;
                l = tid + 128;
                rr = l >> 3; kc = (l & 7) << 2;
                Ast[nbuf][kc + 0][rr] = pa1.x;
                Ast[nbuf][kc + 1][rr] = pa1.y;
                Ast[nbuf][kc + 2][rr] = pa1.z;
                Ast[nbuf][kc + 3][rr] = pa1.w;
            }
            cp_async_wait0();
            __syncthreads();
        }
    }

    // epilogue: unpack row pairs, float4 per row into partial buffer
    float* p = g_part[ksplit] + (size_t)(rowbase + w * 8) * BN + lane * 4;
    #pragma unroll
    for (int rp = 0; rp < 4; ++rp) {
        float2 c0 = unpk2(acc[rp][0]);
        float2 c1 = unpk2(acc[rp][1]);
        float2 c2 = unpk2(acc[rp][2]);
        float2 c3 = unpk2(acc[rp][3]);
        *(float4*)(p + (size_t)(2 * rp) * BN)     = make_float4(c0.x, c1.x, c2.x, c3.x);
        *(float4*)(p + (size_t)(2 * rp + 1) * BN) = make_float4(c0.y, c1.y, c2.y, c3.y);
    }
}

// ---------------------------------------------------------------------------
// Reduce: out = p0 + p1 + p2 + p3. One float4 per thread (grid 640 x 256).
// ---------------------------------------------------------------------------
__global__ void __launch_bounds__(256) reduce_kernel(float* __restrict__ out) {
    const int idx = blockIdx.x * 256 + threadIdx.x;   // float4 index
    const float4* p0 = (const float4*)g_part[0];
    const float4* p1 = (const float4*)g_part[1];
    const float4* p2 = (const float4*)g_part[2];
    const float4* p3 = (const float4*)g_part[3];
    float4 a = p0[idx], b = p1[idx], c = p2[idx], d = p3[idx];
    float4 r;
    r.x = (a.x + b.x) + (c.x + d.x);
    r.y = (a.y + b.y) + (c.y + d.y);
    r.z = (a.z + b.z) + (c.z + d.z);
    r.w = (a.w + b.w) + (c.w + d.w);
    ((float4*)out)[idx] = r;
}

// ---------------------------------------------------------------------------
// kernel_launch: [weff-build + gather] -> K-split GEMM -> reduce
// ---------------------------------------------------------------------------
extern "C" void kernel_launch(void* const* d_in, const int* in_sizes, int n_in,
                              void* d_out, int out_size) {
    const float* emb   = (const float*)d_in[0];
    const float* Wrel  = (const float*)d_in[1];
    const float* Wcite = (const float*)d_in[2];
    const void*  nbr   = d_in[3];
    const void*  cnt   = d_in[4];
    float* out = (float*)d_out;

    gather_mean_kernel<<<NWEFF_BLK + YY * RR * BB, 128>>>(emb, nbr, cnt, Wrel, Wcite);

    gemm_partial_kernel<<<(MTOT / BM) * NSPLIT, 128>>>();

    reduce_kernel<<<(MTOT * II) / (256 * 4), 256>>>(out);
}